// round 3
// baseline (speedup 1.0000x reference)
#include <cuda_runtime.h>
#include <cstdint>

#define M_DIM 8192
#define N_DIM 4096
#define K_DIM 4096

#define MT 256
#define NT 128
#define KT 32
#define STAGES 4
#define KITERS (K_DIM / KT)          // 128
#define THREADS 512

#define A_STAGE_BYTES (MT * KT * 4)  // 32768
#define B_STAGE_BYTES (NT * KT * 4)  // 16384
#define STAGE_BYTES   (A_STAGE_BYTES + B_STAGE_BYTES)   // 49152
#define SMEM_BYTES    (STAGES * STAGE_BYTES)            // 196608

// Scratch: k-permuted tf32-rounded copies of x and symmetrized weight
__device__ float g_xperm[(size_t)M_DIM * K_DIM];
__device__ float g_wsym[(size_t)N_DIM * K_DIM];

// ---------------- helpers ----------------
__device__ __forceinline__ uint32_t smem_u32(const void* p) {
    uint32_t a;
    asm("{ .reg .u64 t; cvta.to.shared.u64 t, %1; cvt.u32.u64 %0, t; }" : "=r"(a) : "l"(p));
    return a;
}
__device__ __forceinline__ uint32_t f2tf32(float f) {
    uint32_t r;
    asm("cvt.rna.tf32.f32 %0, %1;" : "=r"(r) : "f"(f));
    return r;
}
__device__ __forceinline__ void cp_async16(uint32_t dst, const void* src) {
    asm volatile("cp.async.cg.shared.global [%0], [%1], 16;" :: "r"(dst), "l"(src) : "memory");
}
#define CP_COMMIT() asm volatile("cp.async.commit_group;" ::: "memory")
#define CP_WAIT2()  asm volatile("cp.async.wait_group 2;" ::: "memory")

__device__ __forceinline__ uint4 lds128(uint32_t a) {
    uint4 v;
    asm volatile("ld.shared.v4.b32 {%0,%1,%2,%3}, [%4];"
                 : "=r"(v.x), "=r"(v.y), "=r"(v.z), "=r"(v.w) : "r"(a));
    return v;
}

__device__ __forceinline__ void mma_tf32(float* c, uint32_t a0, uint32_t a1,
                                         uint32_t a2, uint32_t a3,
                                         uint32_t b0, uint32_t b1) {
    asm volatile(
        "mma.sync.aligned.m16n8k8.row.col.f32.tf32.tf32.f32 "
        "{%0,%1,%2,%3}, {%4,%5,%6,%7}, {%8,%9}, {%0,%1,%2,%3};"
        : "+f"(c[0]), "+f"(c[1]), "+f"(c[2]), "+f"(c[3])
        : "r"(a0), "r"(a1), "r"(a2), "r"(a3), "r"(b0), "r"(b1));
}

// chunk swizzle: row-dependent permutation of the 8 16B chunks in a 128B row
__device__ __forceinline__ uint32_t sws(int r) {
    return (uint32_t)(((r & 1) << 2) | ((r >> 1) & 3));
}

// ---------------- pre-pass: permute + tf32-round x ----------------
// Within each 16-float group, position p holds original k = (p&3)*4 + (p>>2)
// (involution). So thread tig's v4 at chunk tig = {k=tig, tig+4, tig+8, tig+12}.
__global__ void permute_x_kernel(const float* __restrict__ x) {
    int idx = blockIdx.x * blockDim.x + threadIdx.x;    // 0 .. 33554431
    int col = idx & (K_DIM - 1);
    int p = col & 15;
    int srccol = (col & ~15) | ((p & 3) << 2) | (p >> 2);
    size_t row = (size_t)(idx >> 12);
    ((uint32_t*)g_xperm)[idx] = f2tf32(x[row * K_DIM + srccol]);
}

// ---------------- pre-pass: symmetrize + permute + round weight ----------------
__global__ void symmetrize_kernel(const float* __restrict__ w) {
    int idx = blockIdx.x * blockDim.x + threadIdx.x;    // 0 .. 16777215
    int col = idx & (K_DIM - 1);
    int p = col & 15;
    int c = (col & ~15) | ((p & 3) << 2) | (p >> 2);    // source column (pre-permute)
    int r = idx >> 12;
    float v;
    if (r < 4092 && c < 4092) {
        int br = r / 12, ir = r - br * 12;
        int bc = c / 12, ic = c - bc * 12;
        float a = w[(size_t)r * K_DIM + c];
        float b = w[(size_t)(br * 12 + ic) * K_DIM + (bc * 12 + ir)];
        v = 0.5f * (a + b);
    } else {
        v = w[(size_t)r * K_DIM + c];
    }
    ((uint32_t*)g_wsym)[idx] = f2tf32(v);
}

// ---------------- main GEMM ----------------
__global__ void __launch_bounds__(THREADS, 1)
gemm_tf32_kernel(const float* __restrict__ bias, float* __restrict__ out) {
    extern __shared__ char smem[];
    const uint32_t sb = smem_u32(smem);

    const int tid = threadIdx.x;
    const int wid = tid >> 5;
    const int lane = tid & 31;
    const int g = lane >> 2;        // groupID 0..7
    const int tig = lane & 3;       // thread-in-group 0..3

    // warp tile 64x32; warp grid 4 (m) x 4 (n)
    const int wm = (wid & 3) * 64;
    const int wn = (wid >> 2) * 32;

    // CTA raster: bands of 4 M-tiles over all N (keeps W band L2-resident)
    const int num_n = N_DIM / NT;              // 32
    const int tiles_per_band = 4 * num_n;      // 128
    int t = blockIdx.x;
    int band = t / tiles_per_band;
    int inb = t - band * tiles_per_band;
    const int m0 = (band * 4 + (inb & 3)) * MT;
    const int n0 = (inb >> 2) * NT;

    float acc[4][4][4];
    #pragma unroll
    for (int mt = 0; mt < 4; mt++)
        #pragma unroll
        for (int nt = 0; nt < 4; nt++)
            #pragma unroll
            for (int i = 0; i < 4; i++) acc[mt][nt][i] = 0.0f;

    // producer assignment: 16B chunks. A: 2048 chunks (4/thread), B: 1024 (2/thread)
    auto issue_stage = [&](int s, int kt) {
        const uint32_t aBase = sb + (uint32_t)s * STAGE_BYTES;
        const uint32_t bBase = aBase + A_STAGE_BYTES;
        const int k0 = kt * KT;
        #pragma unroll
        for (int i = 0; i < 4; i++) {
            int id = tid + i * THREADS;
            int row = id >> 3, ch = id & 7;
            const float* src = g_xperm + (size_t)(m0 + row) * K_DIM + k0 + ch * 4;
            cp_async16(aBase + (uint32_t)row * 128u + ((ch ^ sws(row)) << 4), src);
        }
        #pragma unroll
        for (int i = 0; i < 2; i++) {
            int id = tid + i * THREADS;
            int row = id >> 3, ch = id & 7;
            const float* src = g_wsym + (size_t)(n0 + row) * K_DIM + k0 + ch * 4;
            cp_async16(bBase + (uint32_t)row * 128u + ((ch ^ sws(row)) << 4), src);
        }
        CP_COMMIT();
    };

    issue_stage(0, 0);
    issue_stage(1, 1);
    issue_stage(2, 2);

    for (int kt = 0; kt < KITERS; kt++) {
        CP_WAIT2();
        __syncthreads();

        if (kt + 3 < KITERS) issue_stage((kt + 3) & 3, kt + 3);
        else CP_COMMIT();

        const int s = kt & 3;
        const uint32_t aStage = sb + (uint32_t)s * STAGE_BYTES;
        const uint32_t bStage = aStage + A_STAGE_BYTES;

        #pragma unroll
        for (int grp = 0; grp < 2; grp++) {
            // B fragments: one v4 per nt covers 2 k-steps
            uint4 bF[4];
            #pragma unroll
            for (int nt = 0; nt < 4; nt++) {
                int rB = wn + nt * 8 + g;
                uint32_t co = ((((uint32_t)grp ^ (rB & 1)) << 2) |
                               ((uint32_t)tig ^ ((rB >> 1) & 3))) << 4;
                bF[nt] = lds128(bStage + (uint32_t)rB * 128u + co);
            }
            #pragma unroll
            for (int mt = 0; mt < 4; mt++) {
                int rA = wm + mt * 16 + g;
                uint32_t co = ((((uint32_t)grp ^ (rA & 1)) << 2) |
                               ((uint32_t)tig ^ ((rA >> 1) & 3))) << 4;
                uint32_t aAddr = aStage + (uint32_t)rA * 128u + co;
                uint4 alo = lds128(aAddr);
                uint4 ahi = lds128(aAddr + 8u * 128u);
                #pragma unroll
                for (int nt = 0; nt < 4; nt++) {
                    mma_tf32(acc[mt][nt], alo.x, ahi.x, alo.y, ahi.y,
                             bF[nt].x, bF[nt].y);                        // ks even
                    mma_tf32(acc[mt][nt], alo.z, ahi.z, alo.w, ahi.w,
                             bF[nt].z, bF[nt].w);                        // ks odd
                }
            }
        }
    }

    // ---- epilogue: bias + store ----
    #pragma unroll
    for (int mt = 0; mt < 4; mt++) {
        int m = m0 + wm + mt * 16 + g;
        float* r0 = out + (size_t)m * N_DIM + n0 + wn;
        float* r1 = r0 + (size_t)8 * N_DIM;
        #pragma unroll
        for (int nt = 0; nt < 4; nt++) {
            int n = n0 + wn + nt * 8 + 2 * tig;
            float b0 = __ldg(bias + n);
            float b1 = __ldg(bias + n + 1);
            float2 v0, v1;
            v0.x = acc[mt][nt][0] + b0;
            v0.y = acc[mt][nt][1] + b1;
            v1.x = acc[mt][nt][2] + b0;
            v1.y = acc[mt][nt][3] + b1;
            *(float2*)(r0 + nt * 8 + 2 * tig) = v0;
            *(float2*)(r1 + nt * 8 + 2 * tig) = v1;
        }
    }
}

// ---------------- launch ----------------
extern "C" void kernel_launch(void* const* d_in, const int* in_sizes, int n_in,
                              void* d_out, int out_size) {
    const float* x = (const float*)d_in[0];       // [8192, 4096]
    const float* w = (const float*)d_in[1];       // [4096, 4096]
    const float* bias = (const float*)d_in[2];    // [4096]
    float* out = (float*)d_out;                   // [8192, 4096]

    permute_x_kernel<<<(M_DIM * (size_t)K_DIM) / 256, 256>>>(x);
    symmetrize_kernel<<<(N_DIM * (size_t)K_DIM) / 256, 256>>>(w);

    cudaFuncSetAttribute(gemm_tf32_kernel,
                         cudaFuncAttributeMaxDynamicSharedMemorySize, SMEM_BYTES);
    const int grid = (M_DIM / MT) * (N_DIM / NT);  // 1024
    gemm_tf32_kernel<<<grid, THREADS, SMEM_BYTES>>>(bias, out);
}

// round 4
// speedup vs baseline: 1.1339x; 1.1339x over previous
#include <cuda_runtime.h>
#include <cstdint>

#define M_DIM 8192
#define N_DIM 4096
#define K_DIM 4096

#define MT 256
#define NT 128
#define KT 32
#define STAGES 4
#define KITERS (K_DIM / KT)          // 128
#define THREADS 256

#define A_STAGE_BYTES (MT * KT * 4)  // 32768
#define B_STAGE_BYTES (NT * KT * 4)  // 16384
#define STAGE_BYTES   (A_STAGE_BYTES + B_STAGE_BYTES)   // 49152
#define SMEM_BYTES    (STAGES * STAGE_BYTES)            // 196608

// Scratch: k-permuted tf32-rounded copies of x and symmetrized weight.
// Within each 16-float K-group, dst position p holds source k = (p&3)*4 + (p>>2),
// so 16B chunk t = {k=t, t+4, t+8, t+12}: one v4 LDS = a/b fragments for 2 k-steps.
__device__ float g_xperm[(size_t)M_DIM * K_DIM];
__device__ float g_wsym[(size_t)N_DIM * K_DIM];

// ---------------- helpers ----------------
__device__ __forceinline__ uint32_t smem_u32(const void* p) {
    uint32_t a;
    asm("{ .reg .u64 t; cvta.to.shared.u64 t, %1; cvt.u32.u64 %0, t; }" : "=r"(a) : "l"(p));
    return a;
}
__device__ __forceinline__ uint32_t f2tf32(float f) {
    uint32_t r;
    asm("cvt.rna.tf32.f32 %0, %1;" : "=r"(r) : "f"(f));
    return r;
}
__device__ __forceinline__ void cp_async16(uint32_t dst, const void* src) {
    asm volatile("cp.async.cg.shared.global [%0], [%1], 16;" :: "r"(dst), "l"(src) : "memory");
}
#define CP_COMMIT() asm volatile("cp.async.commit_group;" ::: "memory")
#define CP_WAIT2()  asm volatile("cp.async.wait_group 2;" ::: "memory")

__device__ __forceinline__ uint4 lds128(uint32_t a) {
    uint4 v;
    asm volatile("ld.shared.v4.b32 {%0,%1,%2,%3}, [%4];"
                 : "=r"(v.x), "=r"(v.y), "=r"(v.z), "=r"(v.w) : "r"(a));
    return v;
}

__device__ __forceinline__ void mma_tf32(float* c, uint32_t a0, uint32_t a1,
                                         uint32_t a2, uint32_t a3,
                                         uint32_t b0, uint32_t b1) {
    asm volatile(
        "mma.sync.aligned.m16n8k8.row.col.f32.tf32.tf32.f32 "
        "{%0,%1,%2,%3}, {%4,%5,%6,%7}, {%8,%9}, {%0,%1,%2,%3};"
        : "+f"(c[0]), "+f"(c[1]), "+f"(c[2]), "+f"(c[3])
        : "r"(a0), "r"(a1), "r"(a2), "r"(a3), "r"(b0), "r"(b1));
}

// chunk swizzle: row-dependent bijection over the 8 16B chunks of a 128B row
// (distinct for r mod 8 => conflict-free v4 phases for 8 consecutive rows)
__device__ __forceinline__ uint32_t sws(int r) {
    return (uint32_t)(((r & 1) << 2) | ((r >> 1) & 3));
}

// ---------------- pre-pass: permute + tf32-round x (16 floats/thread) ----------------
__global__ void permute_x_kernel(const float* __restrict__ x) {
    size_t t = (size_t)blockIdx.x * blockDim.x + threadIdx.x;   // 2.097M threads
    const float4* src = (const float4*)(x + t * 16);
    float4 s0 = src[0], s1 = src[1], s2 = src[2], s3 = src[3];
    uint4 d0, d1, d2, d3;
    // dst chunk c = {src[c], src[c+4], src[c+8], src[c+12]} (register transpose)
    d0.x = f2tf32(s0.x); d0.y = f2tf32(s1.x); d0.z = f2tf32(s2.x); d0.w = f2tf32(s3.x);
    d1.x = f2tf32(s0.y); d1.y = f2tf32(s1.y); d1.z = f2tf32(s2.y); d1.w = f2tf32(s3.y);
    d2.x = f2tf32(s0.z); d2.y = f2tf32(s1.z); d2.z = f2tf32(s2.z); d2.w = f2tf32(s3.z);
    d3.x = f2tf32(s0.w); d3.y = f2tf32(s1.w); d3.z = f2tf32(s2.w); d3.w = f2tf32(s3.w);
    uint4* dst = (uint4*)((uint32_t*)g_xperm + t * 16);
    dst[0] = d0; dst[1] = d1; dst[2] = d2; dst[3] = d3;
}

// ---------------- pre-pass: symmetrize + permute + round weight ----------------
__global__ void symmetrize_kernel(const float* __restrict__ w) {
    int idx = blockIdx.x * blockDim.x + threadIdx.x;    // 0 .. 16777215
    int col = idx & (K_DIM - 1);
    int p = col & 15;
    int c = (col & ~15) | ((p & 3) << 2) | (p >> 2);    // source column (pre-permute)
    int r = idx >> 12;
    float v;
    if (r < 4092 && c < 4092) {
        int br = r / 12, ir = r - br * 12;
        int bc = c / 12, ic = c - bc * 12;
        float a = w[(size_t)r * K_DIM + c];
        float b = w[(size_t)(br * 12 + ic) * K_DIM + (bc * 12 + ir)];
        v = 0.5f * (a + b);
    } else {
        v = w[(size_t)r * K_DIM + c];
    }
    ((uint32_t*)g_wsym)[idx] = f2tf32(v);
}

// ---------------- main GEMM ----------------
__global__ void __launch_bounds__(THREADS, 1)
gemm_tf32_kernel(const float* __restrict__ bias, float* __restrict__ out) {
    extern __shared__ char smem[];
    const uint32_t sb = smem_u32(smem);

    const int tid = threadIdx.x;
    const int wid = tid >> 5;
    const int lane = tid & 31;
    const int g = lane >> 2;        // groupID 0..7
    const int tig = lane & 3;       // thread-in-group 0..3

    // warp tile: 64x64; warp grid 4 (m) x 2 (n)
    const int wm = (wid & 3) * 64;
    const int wn = (wid >> 2) * 64;

    // CTA raster: bands of 4 M-tiles over all N (keeps W band L2-resident)
    const int num_n = N_DIM / NT;              // 32
    const int tiles_per_band = 4 * num_n;      // 128
    int t = blockIdx.x;
    int band = t / tiles_per_band;
    int inb = t - band * tiles_per_band;
    const int m0 = (band * 4 + (inb & 3)) * MT;
    const int n0 = (inb >> 2) * NT;

    // preload bias
    float bias_r[8][2];
    #pragma unroll
    for (int nt = 0; nt < 8; nt++) {
        int n = n0 + wn + nt * 8 + 2 * tig;
        bias_r[nt][0] = __ldg(bias + n);
        bias_r[nt][1] = __ldg(bias + n + 1);
    }

    float acc[4][8][4];
    #pragma unroll
    for (int mt = 0; mt < 4; mt++)
        #pragma unroll
        for (int nt = 0; nt < 8; nt++)
            #pragma unroll
            for (int i = 0; i < 4; i++) acc[mt][nt][i] = 0.0f;

    // producer: A 2048 16B chunks (8/thread), B 1024 (4/thread)
    auto issue_stage = [&](int s, int kt) {
        const uint32_t aBase = sb + (uint32_t)s * STAGE_BYTES;
        const uint32_t bBase = aBase + A_STAGE_BYTES;
        const int k0 = kt * KT;
        #pragma unroll
        for (int i = 0; i < 8; i++) {
            int id = tid + i * THREADS;
            int row = id >> 3, ch = id & 7;
            const float* src = g_xperm + (size_t)(m0 + row) * K_DIM + k0 + ch * 4;
            cp_async16(aBase + (uint32_t)row * 128u + ((ch ^ sws(row)) << 4), src);
        }
        #pragma unroll
        for (int i = 0; i < 4; i++) {
            int id = tid + i * THREADS;
            int row = id >> 3, ch = id & 7;
            const float* src = g_wsym + (size_t)(n0 + row) * K_DIM + k0 + ch * 4;
            cp_async16(bBase + (uint32_t)row * 128u + ((ch ^ sws(row)) << 4), src);
        }
        CP_COMMIT();
    };

    issue_stage(0, 0);
    issue_stage(1, 1);
    issue_stage(2, 2);

    for (int kt = 0; kt < KITERS; kt++) {
        CP_WAIT2();
        __syncthreads();

        if (kt + 3 < KITERS) issue_stage((kt + 3) & 3, kt + 3);
        else CP_COMMIT();

        const int s = kt & 3;
        const uint32_t aStage = sb + (uint32_t)s * STAGE_BYTES;
        const uint32_t bStage = aStage + A_STAGE_BYTES;

        #pragma unroll
        for (int grp = 0; grp < 2; grp++) {   // 16-wide K group => 2 k-steps each
            // B fragments: one v4 per nt covers both k-steps
            uint4 bF[8];
            #pragma unroll
            for (int nt = 0; nt < 8; nt++) {
                int rB = wn + nt * 8 + g;
                uint32_t co = ((((uint32_t)grp ^ (rB & 1)) << 2) |
                               ((uint32_t)tig ^ ((rB >> 1) & 3))) << 4;
                bF[nt] = lds128(bStage + (uint32_t)rB * 128u + co);
            }
            #pragma unroll
            for (int mt = 0; mt < 4; mt++) {
                int rA = wm + mt * 16 + g;
                uint32_t co = ((((uint32_t)grp ^ (rA & 1)) << 2) |
                               ((uint32_t)tig ^ ((rA >> 1) & 3))) << 4;
                uint32_t aAddr = aStage + (uint32_t)rA * 128u + co;
                uint4 alo = lds128(aAddr);
                uint4 ahi = lds128(aAddr + 8u * 128u);
                #pragma unroll
                for (int nt = 0; nt < 8; nt++) {
                    mma_tf32(acc[mt][nt], alo.x, ahi.x, alo.y, ahi.y,
                             bF[nt].x, bF[nt].y);                        // ks even
                    mma_tf32(acc[mt][nt], alo.z, ahi.z, alo.w, ahi.w,
                             bF[nt].z, bF[nt].w);                        // ks odd
                }
            }
        }
    }

    // ---- epilogue: bias + store ----
    #pragma unroll
    for (int mt = 0; mt < 4; mt++) {
        int m = m0 + wm + mt * 16 + g;
        float* r0 = out + (size_t)m * N_DIM + n0 + wn;
        float* r1 = r0 + (size_t)8 * N_DIM;
        #pragma unroll
        for (int nt = 0; nt < 8; nt++) {
            float2 v0, v1;
            v0.x = acc[mt][nt][0] + bias_r[nt][0];
            v0.y = acc[mt][nt][1] + bias_r[nt][1];
            v1.x = acc[mt][nt][2] + bias_r[nt][0];
            v1.y = acc[mt][nt][3] + bias_r[nt][1];
            *(float2*)(r0 + nt * 8 + 2 * tig) = v0;
            *(float2*)(r1 + nt * 8 + 2 * tig) = v1;
        }
    }
}

// ---------------- launch ----------------
extern "C" void kernel_launch(void* const* d_in, const int* in_sizes, int n_in,
                              void* d_out, int out_size) {
    const float* x = (const float*)d_in[0];       // [8192, 4096]
    const float* w = (const float*)d_in[1];       // [4096, 4096]
    const float* bias = (const float*)d_in[2];    // [4096]
    float* out = (float*)d_out;                   // [8192, 4096]

    permute_x_kernel<<<(M_DIM * (size_t)K_DIM) / 16 / 256, 256>>>(x);
    symmetrize_kernel<<<(N_DIM * (size_t)K_DIM) / 256, 256>>>(w);

    cudaFuncSetAttribute(gemm_tf32_kernel,
                         cudaFuncAttributeMaxDynamicSharedMemorySize, SMEM_BYTES);
    const int grid = (M_DIM / MT) * (N_DIM / NT);  // 1024
    gemm_tf32_kernel<<<grid, THREADS, SMEM_BYTES>>>(bias, out);
}

// round 5
// speedup vs baseline: 1.3454x; 1.1865x over previous
#include <cuda_runtime.h>
#include <cstdint>

#define M_DIM 8192
#define N_DIM 4096
#define K_DIM 4096

#define MT 128
#define NT 128
#define KT 32
#define STAGES 3
#define KITERS (K_DIM / KT)          // 128
#define THREADS 128

#define A_STAGE_BYTES (MT * KT * 4)  // 16384
#define B_STAGE_BYTES (NT * KT * 4)  // 16384
#define STAGE_BYTES   (A_STAGE_BYTES + B_STAGE_BYTES)   // 32768
#define SMEM_BYTES    (STAGES * STAGE_BYTES)            // 98304... (3*32768=98304)

// Scratch: symmetrized + tf32-rounded weight
__device__ float g_wsym[(size_t)N_DIM * K_DIM];

// ---------------- helpers ----------------
__device__ __forceinline__ uint32_t smem_u32(const void* p) {
    uint32_t a;
    asm("{ .reg .u64 t; cvta.to.shared.u64 t, %1; cvt.u32.u64 %0, t; }" : "=r"(a) : "l"(p));
    return a;
}
__device__ __forceinline__ uint32_t f2tf32(float f) {
    uint32_t r;
    asm("cvt.rna.tf32.f32 %0, %1;" : "=r"(r) : "f"(f));
    return r;
}
__device__ __forceinline__ void cp_async16(uint32_t dst, const void* src) {
    asm volatile("cp.async.cg.shared.global [%0], [%1], 16;" :: "r"(dst), "l"(src) : "memory");
}
#define CP_COMMIT() asm volatile("cp.async.commit_group;" ::: "memory")
#define CP_WAIT1()  asm volatile("cp.async.wait_group 1;" ::: "memory")

__device__ __forceinline__ uint32_t lds_u32(uint32_t a) {
    uint32_t v;
    asm volatile("ld.shared.b32 %0, [%1];" : "=r"(v) : "r"(a));
    return v;
}

__device__ __forceinline__ void mma_tf32(float* c, const uint32_t* a, const uint32_t* b) {
    asm volatile(
        "mma.sync.aligned.m16n8k8.row.col.f32.tf32.tf32.f32 "
        "{%0,%1,%2,%3}, {%4,%5,%6,%7}, {%8,%9}, {%0,%1,%2,%3};"
        : "+f"(c[0]), "+f"(c[1]), "+f"(c[2]), "+f"(c[3])
        : "r"(a[0]), "r"(a[1]), "r"(a[2]), "r"(a[3]), "r"(b[0]), "r"(b[1]));
}

// swizzled byte offset within a [rows][32 float] tile (128B rows)
__device__ __forceinline__ uint32_t swz(int row, int k) {
    return (uint32_t)row * 128u + (((uint32_t)k * 4u) ^ (((uint32_t)row & 7u) << 4));
}

// ---------------- pre-pass: symmetrize + tf32-round weight ----------------
__global__ void symmetrize_kernel(const float* __restrict__ w) {
    int idx = blockIdx.x * blockDim.x + threadIdx.x;   // 0 .. 16M-1
    int r = idx >> 12;
    int c = idx & (K_DIM - 1);
    float v;
    if (r < 4092 && c < 4092) {
        int br = r / 12, ir = r - br * 12;
        int bc = c / 12, ic = c - bc * 12;
        float a = w[(size_t)r * K_DIM + c];
        float b = w[(size_t)(br * 12 + ic) * K_DIM + (bc * 12 + ir)];
        v = 0.5f * (a + b);
    } else {
        v = w[(size_t)r * K_DIM + c];
    }
    ((uint32_t*)g_wsym)[idx] = f2tf32(v);
}

// ---------------- main GEMM (2 CTAs/SM for bubble overlap) ----------------
__global__ void __launch_bounds__(THREADS, 2)
gemm_tf32_kernel(const float* __restrict__ x, const float* __restrict__ bias,
                 float* __restrict__ out) {
    extern __shared__ char smem[];
    const uint32_t sb = smem_u32(smem);

    const int tid = threadIdx.x;
    const int wid = tid >> 5;
    const int lane = tid & 31;
    const int g = lane >> 2;        // groupID 0..7
    const int tig = lane & 3;       // thread-in-group 0..3

    // warp tile: 64x64; warp grid 2 (m) x 2 (n)
    const int wm = (wid & 1) * 64;
    const int wn = (wid >> 1) * 64;

    // CTA raster: bands of 8 M-tiles over all N (keeps W band L2-resident)
    const int num_n = N_DIM / NT;              // 32
    const int tiles_per_band = 8 * num_n;      // 256
    int t = blockIdx.x;
    int band = t / tiles_per_band;
    int inb = t - band * tiles_per_band;
    const int m0 = (band * 8 + (inb & 7)) * MT;
    const int n0 = (inb >> 3) * NT;

    // preload bias
    float bias_r[8][2];
    #pragma unroll
    for (int nt = 0; nt < 8; nt++) {
        int n = n0 + wn + nt * 8 + 2 * tig;
        bias_r[nt][0] = __ldg(bias + n);
        bias_r[nt][1] = __ldg(bias + n + 1);
    }

    float acc[4][8][4];
    #pragma unroll
    for (int mt = 0; mt < 4; mt++)
        #pragma unroll
        for (int nt = 0; nt < 8; nt++)
            #pragma unroll
            for (int i = 0; i < 4; i++) acc[mt][nt][i] = 0.0f;

    // producer: A 1024 16B chunks (8/thread), B 1024 (8/thread)
    auto issue_stage = [&](int s, int kt) {
        const uint32_t aBase = sb + (uint32_t)s * STAGE_BYTES;
        const uint32_t bBase = aBase + A_STAGE_BYTES;
        const int k0 = kt * KT;
        #pragma unroll
        for (int i = 0; i < 8; i++) {
            int id = tid + i * THREADS;          // 0..1023
            int row = id >> 3, ch = id & 7;
            const float* src = x + (size_t)(m0 + row) * K_DIM + k0 + ch * 4;
            cp_async16(aBase + (uint32_t)row * 128u + (uint32_t)((ch ^ (row & 7)) << 4), src);
        }
        #pragma unroll
        for (int i = 0; i < 8; i++) {
            int id = tid + i * THREADS;          // 0..1023
            int row = id >> 3, ch = id & 7;
            const float* src = g_wsym + (size_t)(n0 + row) * K_DIM + k0 + ch * 4;
            cp_async16(bBase + (uint32_t)row * 128u + (uint32_t)((ch ^ (row & 7)) << 4), src);
        }
        CP_COMMIT();
    };

    // prologue: fill 2 of 3 stages
    issue_stage(0, 0);
    issue_stage(1, 1);

    int s = 0;
    for (int kt = 0; kt < KITERS; kt++) {
        CP_WAIT1();
        __syncthreads();

        if (kt + 2 < KITERS) {
            int ws = s + 2; if (ws >= STAGES) ws -= STAGES;
            issue_stage(ws, kt + 2);
        } else {
            CP_COMMIT();   // keep group count consistent
        }

        const uint32_t aW = sb + (uint32_t)s * STAGE_BYTES + (uint32_t)wm * 128u;
        const uint32_t bW = sb + (uint32_t)s * STAGE_BYTES + A_STAGE_BYTES + (uint32_t)wn * 128u;

        #pragma unroll
        for (int ks = 0; ks < 4; ks++) {
            const int kb = ks * 8;
            uint32_t af[4][4];
            uint32_t bf[8][2];
            #pragma unroll
            for (int mt = 0; mt < 4; mt++) {
                int r = mt * 16 + g;
                af[mt][0] = lds_u32(aW + swz(r,     kb + tig));
                af[mt][1] = lds_u32(aW + swz(r + 8, kb + tig));
                af[mt][2] = lds_u32(aW + swz(r,     kb + tig + 4));
                af[mt][3] = lds_u32(aW + swz(r + 8, kb + tig + 4));
            }
            #pragma unroll
            for (int nt = 0; nt < 8; nt++) {
                int r = nt * 8 + g;
                bf[nt][0] = lds_u32(bW + swz(r, kb + tig));
                bf[nt][1] = lds_u32(bW + swz(r, kb + tig + 4));
            }
            #pragma unroll
            for (int mt = 0; mt < 4; mt++)
                #pragma unroll
                for (int nt = 0; nt < 8; nt++)
                    mma_tf32(acc[mt][nt], af[mt], bf[nt]);
        }

        if (++s == STAGES) s = 0;
    }

    // ---- epilogue: bias + store ----
    #pragma unroll
    for (int mt = 0; mt < 4; mt++) {
        int m = m0 + wm + mt * 16 + g;
        float* r0 = out + (size_t)m * N_DIM + n0 + wn;
        float* r1 = r0 + (size_t)8 * N_DIM;
        #pragma unroll
        for (int nt = 0; nt < 8; nt++) {
            float2 v0, v1;
            v0.x = acc[mt][nt][0] + bias_r[nt][0];
            v0.y = acc[mt][nt][1] + bias_r[nt][1];
            v1.x = acc[mt][nt][2] + bias_r[nt][0];
            v1.y = acc[mt][nt][3] + bias_r[nt][1];
            *(float2*)(r0 + nt * 8 + 2 * tig) = v0;
            *(float2*)(r1 + nt * 8 + 2 * tig) = v1;
        }
    }
}

// ---------------- launch ----------------
extern "C" void kernel_launch(void* const* d_in, const int* in_sizes, int n_in,
                              void* d_out, int out_size) {
    const float* x = (const float*)d_in[0];       // [8192, 4096]
    const float* w = (const float*)d_in[1];       // [4096, 4096]
    const float* bias = (const float*)d_in[2];    // [4096]
    float* out = (float*)d_out;                   // [8192, 4096]

    symmetrize_kernel<<<(N_DIM * (size_t)K_DIM) / 256, 256>>>(w);

    cudaFuncSetAttribute(gemm_tf32_kernel,
                         cudaFuncAttributeMaxDynamicSharedMemorySize, SMEM_BYTES);
    const int grid = (M_DIM / MT) * (N_DIM / NT);  // 2048
    gemm_tf32_kernel<<<grid, THREADS, SMEM_BYTES>>>(x, bias, out);
}

// round 6
// speedup vs baseline: 1.5150x; 1.1261x over previous
#include <cuda_runtime.h>
#include <cstdint>

#define M_DIM 8192
#define N_DIM 4096
#define K_DIM 4096

#define MT 128
#define NT 128
#define KT 32
#define STAGES 3
#define KITERS (K_DIM / KT)          // 128
#define THREADS 128

#define A_STAGE_BYTES (MT * KT * 4)  // 16384
#define B_STAGE_BYTES (NT * KT * 4)  // 16384
#define STAGE_BYTES   (A_STAGE_BYTES + B_STAGE_BYTES)   // 32768
#define SMEM_BYTES    (STAGES * STAGE_BYTES)            // 98304

// Scratch: symmetrized + tf32-rounded weight
__device__ float g_wsym[(size_t)N_DIM * K_DIM];

// ---------------- helpers ----------------
__device__ __forceinline__ uint32_t smem_u32(const void* p) {
    uint32_t a;
    asm("{ .reg .u64 t; cvta.to.shared.u64 t, %1; cvt.u32.u64 %0, t; }" : "=r"(a) : "l"(p));
    return a;
}
__device__ __forceinline__ uint32_t f2tf32(float f) {
    uint32_t r;
    asm("cvt.rna.tf32.f32 %0, %1;" : "=r"(r) : "f"(f));
    return r;
}
__device__ __forceinline__ void cp_async16(uint32_t dst, const void* src) {
    asm volatile("cp.async.cg.shared.global [%0], [%1], 16;" :: "r"(dst), "l"(src) : "memory");
}
#define CP_COMMIT() asm volatile("cp.async.commit_group;" ::: "memory")
#define CP_WAIT1()  asm volatile("cp.async.wait_group 1;" ::: "memory")

// ldmatrix x4: four 8x(16B) matrices -> 4 regs/thread
__device__ __forceinline__ void ldsm4(uint32_t& d0, uint32_t& d1, uint32_t& d2,
                                      uint32_t& d3, uint32_t a) {
    asm volatile("ldmatrix.sync.aligned.m8n8.x4.shared.b16 {%0,%1,%2,%3}, [%4];"
                 : "=r"(d0), "=r"(d1), "=r"(d2), "=r"(d3) : "r"(a));
}

__device__ __forceinline__ void mma_tf32(float* c, const uint32_t* a, const uint32_t* b) {
    asm volatile(
        "mma.sync.aligned.m16n8k8.row.col.f32.tf32.tf32.f32 "
        "{%0,%1,%2,%3}, {%4,%5,%6,%7}, {%8,%9}, {%0,%1,%2,%3};"
        : "+f"(c[0]), "+f"(c[1]), "+f"(c[2]), "+f"(c[3])
        : "r"(a[0]), "r"(a[1]), "r"(a[2]), "r"(a[3]), "r"(b[0]), "r"(b[1]));
}

// ---------------- pre-pass: symmetrize + tf32-round weight ----------------
__global__ void symmetrize_kernel(const float* __restrict__ w) {
    int idx = blockIdx.x * blockDim.x + threadIdx.x;   // 0 .. 16M-1
    int r = idx >> 12;
    int c = idx & (K_DIM - 1);
    float v;
    if (r < 4092 && c < 4092) {
        int br = r / 12, ir = r - br * 12;
        int bc = c / 12, ic = c - bc * 12;
        float a = w[(size_t)r * K_DIM + c];
        float b = w[(size_t)(br * 12 + ic) * K_DIM + (bc * 12 + ir)];
        v = 0.5f * (a + b);
    } else {
        v = w[(size_t)r * K_DIM + c];
    }
    ((uint32_t*)g_wsym)[idx] = f2tf32(v);
}

// ---------------- main GEMM (2 CTAs/SM, ldmatrix operand fetch) ----------------
__global__ void __launch_bounds__(THREADS, 2)
gemm_tf32_kernel(const float* __restrict__ x, const float* __restrict__ bias,
                 float* __restrict__ out) {
    extern __shared__ char smem[];
    const uint32_t sb = smem_u32(smem);

    const int tid = threadIdx.x;
    const int wid = tid >> 5;
    const int lane = tid & 31;
    const int g = lane >> 2;        // groupID 0..7
    const int tig = lane & 3;       // thread-in-group 0..3

    // warp tile: 64x64; warp grid 2 (m) x 2 (n)
    const int wm = (wid & 1) * 64;
    const int wn = (wid >> 1) * 64;

    // ldmatrix per-lane geometry (reproduces the scalar fragment layout):
    // A x4: m0 = rows[0..7]xk_lo -> af0, m1 = rows[8..15]xk_lo -> af1,
    //       m2 = rows[0..7]xk_hi -> af2, m3 = rows[8..15]xk_hi -> af3
    const int lane7 = lane & 7;
    const int laneA_row = ((lane >> 3) & 1) * 8 + lane7;   // row within 16-row block
    const int khalfA = lane >> 4;                           // 0: k chunk lo, 1: hi
    // B x4: m0 = nt rows x k_lo, m1 = nt rows x k_hi, m2 = (nt+1) rows x k_lo, m3 = hi
    const int laneB_row = (lane >> 4) * 8 + lane7;          // row within 16-row (2 nt) block
    const int khalfB = (lane >> 3) & 1;

    // per-ks swizzled chunk byte offsets (chunk c stored at ((c ^ (row&7))<<4))
    uint32_t cA[4], cB[4];
    #pragma unroll
    for (int ks = 0; ks < 4; ks++) {
        cA[ks] = (uint32_t)(((2 * ks + khalfA) ^ lane7) << 4);
        cB[ks] = (uint32_t)(((2 * ks + khalfB) ^ lane7) << 4);
    }

    // CTA raster: bands of 8 M-tiles over all N (keeps W band L2-resident)
    const int num_n = N_DIM / NT;              // 32
    const int tiles_per_band = 8 * num_n;      // 256
    int t = blockIdx.x;
    int band = t / tiles_per_band;
    int inb = t - band * tiles_per_band;
    const int m0 = (band * 8 + (inb & 7)) * MT;
    const int n0 = (inb >> 3) * NT;

    // preload bias
    float bias_r[8][2];
    #pragma unroll
    for (int nt = 0; nt < 8; nt++) {
        int n = n0 + wn + nt * 8 + 2 * tig;
        bias_r[nt][0] = __ldg(bias + n);
        bias_r[nt][1] = __ldg(bias + n + 1);
    }

    float acc[4][8][4];
    #pragma unroll
    for (int mt = 0; mt < 4; mt++)
        #pragma unroll
        for (int nt = 0; nt < 8; nt++)
            #pragma unroll
            for (int i = 0; i < 4; i++) acc[mt][nt][i] = 0.0f;

    // producer: A 1024 16B chunks (8/thread), B 1024 (8/thread)
    auto issue_stage = [&](int s, int kt) {
        const uint32_t aBase = sb + (uint32_t)s * STAGE_BYTES;
        const uint32_t bBase = aBase + A_STAGE_BYTES;
        const int k0 = kt * KT;
        #pragma unroll
        for (int i = 0; i < 8; i++) {
            int id = tid + i * THREADS;          // 0..1023
            int row = id >> 3, ch = id & 7;
            const float* src = x + (size_t)(m0 + row) * K_DIM + k0 + ch * 4;
            cp_async16(aBase + (uint32_t)row * 128u + (uint32_t)((ch ^ (row & 7)) << 4), src);
        }
        #pragma unroll
        for (int i = 0; i < 8; i++) {
            int id = tid + i * THREADS;
            int row = id >> 3, ch = id & 7;
            const float* src = g_wsym + (size_t)(n0 + row) * K_DIM + k0 + ch * 4;
            cp_async16(bBase + (uint32_t)row * 128u + (uint32_t)((ch ^ (row & 7)) << 4), src);
        }
        CP_COMMIT();
    };

    // prologue: fill 2 of 3 stages
    issue_stage(0, 0);
    issue_stage(1, 1);

    int s = 0;
    for (int kt = 0; kt < KITERS; kt++) {
        CP_WAIT1();
        __syncthreads();

        const uint32_t aStage = sb + (uint32_t)s * STAGE_BYTES;
        const uint32_t bStage = aStage + A_STAGE_BYTES;
        const uint32_t aB = aStage + (uint32_t)(wm + laneA_row) * 128u;
        const uint32_t bB = bStage + (uint32_t)(wn + laneB_row) * 128u;

        #pragma unroll
        for (int ks = 0; ks < 4; ks++) {
            uint32_t af[4][4];
            uint32_t bf[8][2];
            #pragma unroll
            for (int mt = 0; mt < 4; mt++)
                ldsm4(af[mt][0], af[mt][1], af[mt][2], af[mt][3],
                      aB + (uint32_t)mt * 2048u + cA[ks]);
            #pragma unroll
            for (int p = 0; p < 4; p++)
                ldsm4(bf[2 * p][0], bf[2 * p][1], bf[2 * p + 1][0], bf[2 * p + 1][1],
                      bB + (uint32_t)p * 2048u + cB[ks]);
            #pragma unroll
            for (int mt = 0; mt < 4; mt++)
                #pragma unroll
                for (int nt = 0; nt < 8; nt++)
                    mma_tf32(acc[mt][nt], af[mt], bf[nt]);

            if (ks == 0) {   // overlap cp.async issue with MMA work
                if (kt + 2 < KITERS) {
                    int ws = s + 2; if (ws >= STAGES) ws -= STAGES;
                    issue_stage(ws, kt + 2);
                } else {
                    CP_COMMIT();   // keep group count consistent
                }
            }
        }

        if (++s == STAGES) s = 0;
    }

    // ---- epilogue: bias + store ----
    #pragma unroll
    for (int mt = 0; mt < 4; mt++) {
        int m = m0 + wm + mt * 16 + g;
        float* r0 = out + (size_t)m * N_DIM + n0 + wn;
        float* r1 = r0 + (size_t)8 * N_DIM;
        #pragma unroll
        for (int nt = 0; nt < 8; nt++) {
            float2 v0, v1;
            v0.x = acc[mt][nt][0] + bias_r[nt][0];
            v0.y = acc[mt][nt][1] + bias_r[nt][1];
            v1.x = acc[mt][nt][2] + bias_r[nt][0];
            v1.y = acc[mt][nt][3] + bias_r[nt][1];
            *(float2*)(r0 + nt * 8 + 2 * tig) = v0;
            *(float2*)(r1 + nt * 8 + 2 * tig) = v1;
        }
    }
}

// ---------------- launch ----------------
extern "C" void kernel_launch(void* const* d_in, const int* in_sizes, int n_in,
                              void* d_out, int out_size) {
    const float* x = (const float*)d_in[0];       // [8192, 4096]
    const float* w = (const float*)d_in[1];       // [4096, 4096]
    const float* bias = (const float*)d_in[2];    // [4096]
    float* out = (float*)d_out;                   // [8192, 4096]

    symmetrize_kernel<<<(N_DIM * (size_t)K_DIM) / 256, 256>>>(w);

    cudaFuncSetAttribute(gemm_tf32_kernel,
                         cudaFuncAttributeMaxDynamicSharedMemorySize, SMEM_BYTES);
    const int grid = (M_DIM / MT) * (N_DIM / NT);  // 2048
    gemm_tf32_kernel<<<grid, THREADS, SMEM_BYTES>>>(x, bias, out);
}

// round 8
// speedup vs baseline: 1.5345x; 1.0129x over previous
#include <cuda_runtime.h>
#include <cstdint>

#define M_DIM 8192
#define N_DIM 4096
#define K_DIM 4096

#define MT 128
#define NT 128
#define KT 32
#define STAGES 3
#define KITERS (K_DIM / KT)          // 128
#define THREADS 128

#define A_STAGE_BYTES (MT * KT * 4)  // 16384
#define B_STAGE_BYTES (NT * KT * 4)  // 16384
#define STAGE_BYTES   (A_STAGE_BYTES + B_STAGE_BYTES)   // 32768
#define TILES_OFF     1024           // barriers live in the first 1KB
#define SMEM_BYTES    (TILES_OFF + STAGES * STAGE_BYTES)  // 99328

// Scratch: symmetrized + tf32-rounded weight
__device__ float g_wsym[(size_t)N_DIM * K_DIM];

// ---------------- helpers ----------------
__device__ __forceinline__ uint32_t smem_u32(const void* p) {
    uint32_t a;
    asm("{ .reg .u64 t; cvta.to.shared.u64 t, %1; cvt.u32.u64 %0, t; }" : "=r"(a) : "l"(p));
    return a;
}
__device__ __forceinline__ uint32_t f2tf32(float f) {
    uint32_t r;
    asm("cvt.rna.tf32.f32 %0, %1;" : "=r"(r) : "f"(f));
    return r;
}
__device__ __forceinline__ void cp_async16(uint32_t dst, const void* src) {
    asm volatile("cp.async.cg.shared.global [%0], [%1], 16;" :: "r"(dst), "l"(src) : "memory");
}
// deferred arrival on mbarrier when all this thread's prior cp.asyncs complete.
// .noinc: the arrive CONSUMES one of the initialized expected arrivals
// (the default non-noinc form is self-balancing and never flips the phase).
__device__ __forceinline__ void cp_async_mbar_arrive(uint32_t bar) {
    asm volatile("cp.async.mbarrier.arrive.noinc.shared.b64 [%0];" :: "r"(bar) : "memory");
}

#define MBARRIER_INIT(addr, cnt) \
    asm volatile("mbarrier.init.shared.b64 [%0], %1;" :: "r"((uint32_t)(addr)), "r"((uint32_t)(cnt)) : "memory")
#define MBARRIER_ARRIVE(addr) \
    asm volatile("mbarrier.arrive.shared.b64 _, [%0];" :: "r"((uint32_t)(addr)) : "memory")

#define MBARRIER_WAIT_PARITY(mbar_addr, phase_parity) do {                                   \
    uint32_t _mbar = (uint32_t)(mbar_addr);                                                  \
    uint32_t _par  = (uint32_t)(phase_parity);                                               \
    uint32_t _done;                                                                          \
    asm volatile(                                                                            \
        "{\n\t.reg .pred p;\n\t"                                                             \
        "mbarrier.try_wait.parity.acquire.cta.shared::cta.b64 p, [%1], %2;\n\t"              \
        "selp.b32 %0, 1, 0, p;\n\t}"                                                         \
        : "=r"(_done) : "r"(_mbar), "r"(_par) : "memory");                                   \
    if (!_done) {                                                                            \
        asm volatile(                                                                        \
            "{\n\t.reg .pred P1;\n\t"                                                        \
            "WAIT_LOOP_%=:\n\t"                                                              \
            "mbarrier.try_wait.parity.acquire.cta.shared::cta.b64 P1, [%0], %1, 0x989680;\n\t" \
            "@P1 bra.uni WAIT_DONE_%=;\n\t"                                                  \
            "bra.uni WAIT_LOOP_%=;\n\t"                                                      \
            "WAIT_DONE_%=:\n\t}"                                                             \
            :: "r"(_mbar), "r"(_par) : "memory");                                            \
    }                                                                                        \
} while (0)

// ldmatrix x4: four 8x(16B) matrices -> 4 regs/thread
__device__ __forceinline__ void ldsm4(uint32_t& d0, uint32_t& d1, uint32_t& d2,
                                      uint32_t& d3, uint32_t a) {
    asm volatile("ldmatrix.sync.aligned.m8n8.x4.shared.b16 {%0,%1,%2,%3}, [%4];"
                 : "=r"(d0), "=r"(d1), "=r"(d2), "=r"(d3) : "r"(a));
}

__device__ __forceinline__ void mma_tf32(float* c, const uint32_t* a, const uint32_t* b) {
    asm volatile(
        "mma.sync.aligned.m16n8k8.row.col.f32.tf32.tf32.f32 "
        "{%0,%1,%2,%3}, {%4,%5,%6,%7}, {%8,%9}, {%0,%1,%2,%3};"
        : "+f"(c[0]), "+f"(c[1]), "+f"(c[2]), "+f"(c[3])
        : "r"(a[0]), "r"(a[1]), "r"(a[2]), "r"(a[3]), "r"(b[0]), "r"(b[1]));
}

// ---------------- pre-pass: symmetrize + tf32-round weight (float4) ----------------
__global__ void symmetrize_kernel(const float* __restrict__ w) {
    int idx = blockIdx.x * blockDim.x + threadIdx.x;   // 0 .. 4,194,303
    int r = idx >> 10;                                 // 1024 float4 per row
    int c4 = (idx & 1023) * 4;
    float4 a = *(const float4*)(w + (size_t)r * K_DIM + c4);
    float o[4] = {a.x, a.y, a.z, a.w};
    if (r < 4092 && c4 < 4092) {     // 4092 % 4 == 0: group never straddles edge
        int br = r / 12, ir = r - br * 12;
        #pragma unroll
        for (int j = 0; j < 4; j++) {
            int c = c4 + j;
            int bc = c / 12, ic = c - bc * 12;
            float b = w[(size_t)(br * 12 + ic) * K_DIM + bc * 12 + ir];
            o[j] = 0.5f * (o[j] + b);
        }
    }
    uint4 v;
    v.x = f2tf32(o[0]); v.y = f2tf32(o[1]); v.z = f2tf32(o[2]); v.w = f2tf32(o[3]);
    *(uint4*)((uint32_t*)g_wsym + (size_t)r * K_DIM + c4) = v;
}

// ---------------- main GEMM (2 CTAs/SM, ldmatrix, async mbarrier pipeline) ----------------
__global__ void __launch_bounds__(THREADS, 2)
gemm_tf32_kernel(const float* __restrict__ x, const float* __restrict__ bias,
                 float* __restrict__ out) {
    extern __shared__ __align__(1024) char smem[];
    const uint32_t sb = smem_u32(smem);

    const int tid = threadIdx.x;
    const int wid = tid >> 5;
    const int lane = tid & 31;
    const int g = lane >> 2;
    const int tig = lane & 3;

    // barrier addresses
    const uint32_t fullB = sb;            // STAGES x 8B
    const uint32_t emptyB = sb + 64;      // STAGES x 8B
    const uint32_t tiles = sb + TILES_OFF;

    // warp tile: 64x64; warp grid 2 (m) x 2 (n)
    const int wm = (wid & 1) * 64;
    const int wn = (wid >> 1) * 64;

    // ldmatrix per-lane geometry (same fragment layout as scalar path)
    const int lane7 = lane & 7;
    const int laneA_row = ((lane >> 3) & 1) * 8 + lane7;
    const int khalfA = lane >> 4;
    const int laneB_row = (lane >> 4) * 8 + lane7;
    const int khalfB = (lane >> 3) & 1;

    uint32_t cA[4], cB[4];
    #pragma unroll
    for (int ks = 0; ks < 4; ks++) {
        cA[ks] = (uint32_t)(((2 * ks + khalfA) ^ lane7) << 4);
        cB[ks] = (uint32_t)(((2 * ks + khalfB) ^ lane7) << 4);
    }

    // CTA raster: bands of 8 M-tiles over all N
    const int num_n = N_DIM / NT;              // 32
    const int tiles_per_band = 8 * num_n;      // 256
    int t = blockIdx.x;
    int band = t / tiles_per_band;
    int inb = t - band * tiles_per_band;
    const int m0 = (band * 8 + (inb & 7)) * MT;
    const int n0 = (inb >> 3) * NT;

    // init barriers
    if (tid == 0) {
        #pragma unroll
        for (int s = 0; s < STAGES; s++) {
            MBARRIER_INIT(fullB + s * 8, THREADS);  // one cp.async arrival per thread
            MBARRIER_INIT(emptyB + s * 8, 4);       // one arrival per warp
        }
    }
    __syncthreads();

    // preload bias
    float bias_r[8][2];
    #pragma unroll
    for (int nt = 0; nt < 8; nt++) {
        int n = n0 + wn + nt * 8 + 2 * tig;
        bias_r[nt][0] = __ldg(bias + n);
        bias_r[nt][1] = __ldg(bias + n + 1);
    }

    float acc[4][8][4];
    #pragma unroll
    for (int mt = 0; mt < 4; mt++)
        #pragma unroll
        for (int nt = 0; nt < 8; nt++)
            #pragma unroll
            for (int i = 0; i < 4; i++) acc[mt][nt][i] = 0.0f;

    // producer: every thread copies 8 A-chunks + 8 B-chunks (16B each), then
    // posts its deferred arrival on full[stage].
    auto issue_stage = [&](int s, int kt) {
        const uint32_t aBase = tiles + (uint32_t)s * STAGE_BYTES;
        const uint32_t bBase = aBase + A_STAGE_BYTES;
        const int k0 = kt * KT;
        #pragma unroll
        for (int i = 0; i < 8; i++) {
            int id = tid + i * THREADS;
            int row = id >> 3, ch = id & 7;
            const float* src = x + (size_t)(m0 + row) * K_DIM + k0 + ch * 4;
            cp_async16(aBase + (uint32_t)row * 128u + (uint32_t)((ch ^ (row & 7)) << 4), src);
        }
        #pragma unroll
        for (int i = 0; i < 8; i++) {
            int id = tid + i * THREADS;
            int row = id >> 3, ch = id & 7;
            const float* src = g_wsym + (size_t)(n0 + row) * K_DIM + k0 + ch * 4;
            cp_async16(bBase + (uint32_t)row * 128u + (uint32_t)((ch ^ (row & 7)) << 4), src);
        }
        cp_async_mbar_arrive(fullB + s * 8);
    };

    // producer cursor (phase starts 1: first STAGES empty-waits pass immediately)
    int ps = 0, pph = 1;
    // prologue: fill 2 of 3 stages
    issue_stage(0, 0); if (++ps == STAGES) { ps = 0; pph ^= 1; }
    issue_stage(1, 1); if (++ps == STAGES) { ps = 0; pph ^= 1; }

    // consumer cursor
    int s = 0, cph = 0;
    for (int kt = 0; kt < KITERS; kt++) {
        MBARRIER_WAIT_PARITY(fullB + s * 8, cph);

        const uint32_t aStage = tiles + (uint32_t)s * STAGE_BYTES;
        const uint32_t bStage = aStage + A_STAGE_BYTES;
        const uint32_t aB = aStage + (uint32_t)(wm + laneA_row) * 128u;
        const uint32_t bB = bStage + (uint32_t)(wn + laneB_row) * 128u;

        #pragma unroll
        for (int ks = 0; ks < 4; ks++) {
            uint32_t af[4][4];
            uint32_t bf[8][2];
            #pragma unroll
            for (int mt = 0; mt < 4; mt++)
                ldsm4(af[mt][0], af[mt][1], af[mt][2], af[mt][3],
                      aB + (uint32_t)mt * 2048u + cA[ks]);
            #pragma unroll
            for (int p = 0; p < 4; p++)
                ldsm4(bf[2 * p][0], bf[2 * p][1], bf[2 * p + 1][0], bf[2 * p + 1][1],
                      bB + (uint32_t)p * 2048u + cB[ks]);
            #pragma unroll
            for (int mt = 0; mt < 4; mt++)
                #pragma unroll
                for (int nt = 0; nt < 8; nt++)
                    mma_tf32(acc[mt][nt], af[mt], bf[nt]);

            if (ks == 0 && kt + 2 < KITERS) {   // overlap produce with MMA work
                MBARRIER_WAIT_PARITY(emptyB + ps * 8, pph);
                issue_stage(ps, kt + 2);
                if (++ps == STAGES) { ps = 0; pph ^= 1; }
            }
        }

        // release stage: one arrival per warp (arrive has release semantics,
        // ordering this warp's ldmatrix reads before producers overwrite)
        __syncwarp();
        if (lane == 0) MBARRIER_ARRIVE(emptyB + s * 8);

        if (++s == STAGES) { s = 0; cph ^= 1; }
    }

    // ---- epilogue: bias + store ----
    #pragma unroll
    for (int mt = 0; mt < 4; mt++) {
        int m = m0 + wm + mt * 16 + g;
        float* r0 = out + (size_t)m * N_DIM + n0 + wn;
        float* r1 = r0 + (size_t)8 * N_DIM;
        #pragma unroll
        for (int nt = 0; nt < 8; nt++) {
            float2 v0, v1;
            v0.x = acc[mt][nt][0] + bias_r[nt][0];
            v0.y = acc[mt][nt][1] + bias_r[nt][1];
            v1.x = acc[mt][nt][2] + bias_r[nt][0];
            v1.y = acc[mt][nt][3] + bias_r[nt][1];
            *(float2*)(r0 + nt * 8 + 2 * tig) = v0;
            *(float2*)(r1 + nt * 8 + 2 * tig) = v1;
        }
    }
}

// ---------------- launch ----------------
extern "C" void kernel_launch(void* const* d_in, const int* in_sizes, int n_in,
                              void* d_out, int out_size) {
    const float* x = (const float*)d_in[0];       // [8192, 4096]
    const float* w = (const float*)d_in[1];       // [4096, 4096]
    const float* bias = (const float*)d_in[2];    // [4096]
    float* out = (float*)d_out;                   // [8192, 4096]

    symmetrize_kernel<<<(N_DIM * (size_t)K_DIM) / 4 / 256, 256>>>(w);

    cudaFuncSetAttribute(gemm_tf32_kernel,
                         cudaFuncAttributeMaxDynamicSharedMemorySize, SMEM_BYTES);
    const int grid = (M_DIM / MT) * (N_DIM / NT);  // 2048
    gemm_tf32_kernel<<<grid, THREADS, SMEM_BYTES>>>(x, bias, out);
}